// round 15
// baseline (speedup 1.0000x reference)
#include <cuda_runtime.h>
#include <cuda_fp16.h>
#include <cstdint>

#define SNUM 65536
#define MDIM 256
#define ENUM 8
#define HDIM 1024
#define CAP  20480          // TOP_K * int(1.25 * S/E)
#define NB   8192           // gating blocks, 8 tokens each
#define NSEG 128            // scan segments (64 gating blocks each)

// ---------------- scratch (device globals; no allocations allowed) ----------
__device__ int   g_topi[SNUM * 2];
__device__ float g_topv[SNUM * 2];
__device__ int   g_blockcnt[NB * 16];
__device__ int   g_blockoff[NB * 16];     // local exclusive within segment
__device__ float g_blockgate[NB * ENUM];
__device__ int   g_segsum[NSEG * 16];
__device__ int   g_segoff[NSEG * 16];     // exclusive across segments
__device__ float g_gatepart[NSEG * ENUM];
__device__ int   g_k1base[ENUM];
__device__ int   g_cnt[ENUM];
__device__ int   g_src[ENUM * CAP];
__device__ int   g_tokslot[SNUM * 2];
__device__ __half g_xh [(size_t)SNUM * MDIM];          // fp16 x
__device__ __half g_w1t[(size_t)ENUM * HDIM * MDIM];   // [E][1024][256] fp16
__device__ __half g_w2t[(size_t)ENUM * MDIM * HDIM];   // [E][256][1024] fp16
__device__ __half g_h [(size_t)ENUM * CAP * HDIM];     // hidden fp16
__device__ __half g_eo[(size_t)ENUM * CAP * MDIM];     // expert outputs fp16

// ---------------- helpers ----------------------------------------------------
__device__ __forceinline__ uint32_t smem_to_u32(const void* p) {
    uint32_t a;
    asm("{ .reg .u64 t; cvta.to.shared.u64 t, %1; cvt.u32.u64 %0, t; }" : "=r"(a) : "l"(p));
    return a;
}
__device__ __forceinline__ void cp16(uint32_t dst, const void* src) {
    asm volatile("cp.async.cg.shared.global [%0], [%1], 16;" :: "r"(dst), "l"(src) : "memory");
}
#define CP_COMMIT() asm volatile("cp.async.commit_group;" ::: "memory")

__device__ __forceinline__ void ldsm4(uint32_t* r, uint32_t addr) {
    asm volatile("ldmatrix.sync.aligned.m8n8.x4.shared.b16 {%0,%1,%2,%3}, [%4];"
                 : "=r"(r[0]), "=r"(r[1]), "=r"(r[2]), "=r"(r[3]) : "r"(addr));
}
__device__ __forceinline__ void ldsm2(uint32_t* r, uint32_t addr) {
    asm volatile("ldmatrix.sync.aligned.m8n8.x2.shared.b16 {%0,%1}, [%2];"
                 : "=r"(r[0]), "=r"(r[1]) : "r"(addr));
}
__device__ __forceinline__ void mma_f16(float* c, const uint32_t* a, const uint32_t* b) {
    asm volatile("mma.sync.aligned.m16n8k16.row.col.f32.f16.f16.f32 "
                 "{%0,%1,%2,%3}, {%4,%5,%6,%7}, {%8,%9}, {%0,%1,%2,%3};"
                 : "+f"(c[0]), "+f"(c[1]), "+f"(c[2]), "+f"(c[3])
                 : "r"(a[0]), "r"(a[1]), "r"(a[2]), "r"(a[3]), "r"(b[0]), "r"(b[1]));
}

// ---------------- 0) transpose + fp16 weights --------------------------------
__global__ void k_transpose(const float* __restrict__ in, __half* __restrict__ out,
                            int R, int C) {
    __shared__ float t[32][33];
    int e = blockIdx.z;
    const float* ine = in + (size_t)e * R * C;
    __half* oute = out + (size_t)e * R * C;
    int c0 = blockIdx.x * 32, r0 = blockIdx.y * 32;
    int tx = threadIdx.x, ty = threadIdx.y;
#pragma unroll
    for (int i = 0; i < 4; i++)
        t[ty + i * 8][tx] = ine[(size_t)(r0 + ty + i * 8) * C + c0 + tx];
    __syncthreads();
#pragma unroll
    for (int i = 0; i < 4; i++)
        oute[(size_t)(c0 + ty + i * 8) * R + r0 + tx] = __float2half_rn(t[tx][ty + i * 8]);
}

// ---------------- 1) gating (also emits fp16 x) ------------------------------
__global__ __launch_bounds__(256) void k_gate(const float* __restrict__ x,
                                              const float* __restrict__ wg) {
    __shared__ float wgs[ENUM * MDIM];
    __shared__ int   scnt[16];
    __shared__ float sg[8][ENUM];
    int tid = threadIdx.x;
    for (int i = tid; i < ENUM * MDIM; i += 256) wgs[i] = wg[i];
    if (tid < 16) scnt[tid] = 0;
    __syncthreads();

    int warp = tid >> 5, lane = tid & 31;
    int s = blockIdx.x * 8 + warp;
    const float* xr = x + (size_t)s * MDIM;

    float part[ENUM];
#pragma unroll
    for (int e = 0; e < ENUM; e++) part[e] = 0.f;
#pragma unroll
    for (int i = 0; i < 8; i++) {
        float v = xr[i * 32 + lane];
#pragma unroll
        for (int e = 0; e < ENUM; e++) part[e] += v * wgs[e * MDIM + i * 32 + lane];
    }
    // fused x -> fp16 (row is hot in L1)
    {
        float4 a0 = *(const float4*)(xr + lane * 8);
        float4 a1 = *(const float4*)(xr + lane * 8 + 4);
        __half2 hh[4];
        hh[0] = __floats2half2_rn(a0.x, a0.y);
        hh[1] = __floats2half2_rn(a0.z, a0.w);
        hh[2] = __floats2half2_rn(a1.x, a1.y);
        hh[3] = __floats2half2_rn(a1.z, a1.w);
        *(uint4*)(g_xh + (size_t)s * MDIM + lane * 8) = *(const uint4*)hh;
    }
#pragma unroll
    for (int e = 0; e < ENUM; e++) {
#pragma unroll
        for (int off = 16; off; off >>= 1)
            part[e] += __shfl_xor_sync(0xffffffffu, part[e], off);
    }

    if (lane == 0) {
        float mx = part[0];
#pragma unroll
        for (int e = 1; e < ENUM; e++) mx = fmaxf(mx, part[e]);
        float p[ENUM]; float sum = 0.f;
#pragma unroll
        for (int e = 0; e < ENUM; e++) { p[e] = expf(part[e] - mx); sum += p[e]; }
        float inv = 1.f / sum;
#pragma unroll
        for (int e = 0; e < ENUM; e++) { p[e] *= inv; sg[warp][e] = p[e]; }
        int i0 = 0; float v0 = p[0];
#pragma unroll
        for (int e = 1; e < ENUM; e++) if (p[e] > v0) { v0 = p[e]; i0 = e; }
        int i1 = -1; float v1 = -1.f;
#pragma unroll
        for (int e = 0; e < ENUM; e++) if (e != i0 && p[e] > v1) { v1 = p[e]; i1 = e; }
        g_topi[s * 2 + 0] = i0;  g_topi[s * 2 + 1] = i1;
        g_topv[s * 2 + 0] = v0;  g_topv[s * 2 + 1] = v1;
        atomicAdd(&scnt[i0 * 2 + 0], 1);
        atomicAdd(&scnt[i1 * 2 + 1], 1);
    }
    __syncthreads();
    if (tid < 16) g_blockcnt[blockIdx.x * 16 + tid] = scnt[tid];
    if (tid < ENUM) {
        float a = 0.f;
#pragma unroll
        for (int w = 0; w < 8; w++) a += sg[w][tid];
        g_blockgate[blockIdx.x * ENUM + tid] = a;
    }
}

// ---------------- 2a) segment scan (parallel) --------------------------------
__global__ __launch_bounds__(512) void k_scanA() {
    int seg = blockIdx.x;
    int tid = threadIdx.x, w = tid >> 5, lane = tid & 31;
    int carry = 0;
#pragma unroll
    for (int c = 0; c < 2; c++) {
        int row = seg * 64 + c * 32 + lane;
        int v = g_blockcnt[row * 16 + w];
        int inc = v;
#pragma unroll
        for (int off = 1; off < 32; off <<= 1) {
            int t = __shfl_up_sync(0xffffffffu, inc, off);
            if (lane >= off) inc += t;
        }
        g_blockoff[row * 16 + w] = carry + inc - v;   // local exclusive
        carry += __shfl_sync(0xffffffffu, inc, 31);
    }
    if (lane == 0) g_segsum[seg * 16 + w] = carry;
    if (w < ENUM) {   // fixed-order segment gate sum
        float a = g_blockgate[(seg * 64 + lane) * ENUM + w]
                + g_blockgate[(seg * 64 + 32 + lane) * ENUM + w];
#pragma unroll
        for (int off = 16; off; off >>= 1)
            a += __shfl_xor_sync(0xffffffffu, a, off);
        if (lane == 0) g_gatepart[seg * ENUM + w] = a;
    }
}

// ---------------- 2b) top-level scan + loss ----------------------------------
__global__ __launch_bounds__(512) void k_scanB(float* lossPtr) {
    int tid = threadIdx.x, w = tid >> 5, lane = tid & 31;
    __shared__ int   s_tot[16];
    __shared__ float s_gs[ENUM];
    int carry = 0;
#pragma unroll
    for (int c = 0; c < NSEG / 32; c++) {
        int seg = c * 32 + lane;
        int v = g_segsum[seg * 16 + w];
        int inc = v;
#pragma unroll
        for (int off = 1; off < 32; off <<= 1) {
            int t = __shfl_up_sync(0xffffffffu, inc, off);
            if (lane >= off) inc += t;
        }
        g_segoff[seg * 16 + w] = carry + inc - v;
        carry += __shfl_sync(0xffffffffu, inc, 31);
    }
    if (lane == 0) s_tot[w] = carry;
    if (w < ENUM) {
        float a = 0.f;
#pragma unroll
        for (int c = 0; c < NSEG / 32; c++)
            a += g_gatepart[(c * 32 + lane) * ENUM + w];
#pragma unroll
        for (int off = 16; off; off >>= 1)
            a += __shfl_xor_sync(0xffffffffu, a, off);
        if (lane == 0) s_gs[w] = a;
    }
    __syncthreads();
    if (tid == 0) {
        float loss = 0.f;
        for (int e = 0; e < ENUM; e++) {
            float me = s_gs[e] / (float)SNUM;
            float ce = (float)s_tot[e * 2] / (float)SNUM;
            loss += me * ce;
        }
        loss *= (float)ENUM;
        if (lossPtr) *lossPtr = loss;
        for (int e = 0; e < ENUM; e++) {
            g_k1base[e] = s_tot[e * 2];
            int t = s_tot[e * 2] + s_tot[e * 2 + 1];
            g_cnt[e] = t < CAP ? t : CAP;
        }
    }
}

// ---------------- 3) routing -------------------------------------------------
__global__ __launch_bounds__(256) void k_route() {
    __shared__ int ch[8][2];
    int tid = threadIdx.x, warp = tid >> 5, lane = tid & 31;
    int s = blockIdx.x * 8 + warp;
    if (lane < 2) ch[warp][lane] = g_topi[s * 2 + lane];
    __syncthreads();
    if (tid < 16) {
        int t = tid >> 1, k = tid & 1;
        int s2 = blockIdx.x * 8 + t;
        int e = ch[t][k];
        int rank = 0;
#pragma unroll
        for (int u = 0; u < 8; u++) rank += (u < t) && (ch[u][k] == e);
        int idx = e * 2 + k;
        int pos = g_blockoff[blockIdx.x * 16 + idx]
                + g_segoff[(blockIdx.x >> 6) * 16 + idx]
                + rank + (k ? g_k1base[e] : 0);
        int slot = -1;
        if (pos < CAP) { slot = e * CAP + pos; g_src[slot] = s2; }
        g_tokslot[s2 * 2 + k] = slot;
    }
}

// ---------------- 4) GEMM1: fp16 mma, tile 128x128x64, 3-stage + frag dbuf --
#define STAGES 3
#define SMEM_BYTES (STAGES * 32768)

template<int NK, int NTOT, bool GATHER, bool RELU>
__global__ __launch_bounds__(256, 2) void k_mma(
    const __half* __restrict__ Ag, const __half* __restrict__ Bg,
    const float* __restrict__ biasG, __half* __restrict__ Cg)
{
    constexpr int KDIM = NK * 64;
    int e = blockIdx.z;
    int cnt = g_cnt[e];
    int row0 = blockIdx.x * 128;
    if (row0 >= cnt) return;
    int j0 = blockIdx.y * 128;

    extern __shared__ char smem[];
    uint32_t sb = smem_to_u32(smem);
    __shared__ int s_src[128];
    int tid = threadIdx.x, warp = tid >> 5, lane = tid & 31;
    int warp_m = warp & 1, warp_n = warp >> 1;

    if (GATHER && tid < 128) {
        int r = row0 + tid;
        s_src[tid] = g_src[e * CAP + (r < cnt ? r : cnt - 1)];
    }
    __syncthreads();

    const __half* aptr[4]; const __half* bptr[4];
    uint32_t adst[4], bdst[4];
#pragma unroll
    for (int it = 0; it < 4; it++) {
        int idx = it * 256 + tid;
        int row = idx >> 3, chunk = idx & 7;
        if (GATHER) {
            aptr[it] = Ag + (size_t)s_src[row] * KDIM + chunk * 8;
        } else {
            int rr = row0 + row; if (rr >= cnt) rr = cnt - 1;
            aptr[it] = Ag + ((size_t)e * CAP + rr) * KDIM + chunk * 8;
        }
        bptr[it] = Bg + ((size_t)e * NTOT + j0 + row) * KDIM + chunk * 8;
        uint32_t sw = (uint32_t)((chunk ^ (row & 7)) << 4);
        adst[it] = sb + row * 128 + sw;
        bdst[it] = sb + 16384 + row * 128 + sw;
    }

    int rowa_b = warp_m * 64 + (lane & 7) + ((lane >> 3) & 1) * 8;
    int kua = lane >> 4;
    int rowb_b = warp_n * 32 + (lane & 7);
    int kub = (lane >> 3) & 1;

    float acc[4][4][4];
#pragma unroll
    for (int mi = 0; mi < 4; mi++)
#pragma unroll
        for (int ni = 0; ni < 4; ni++)
#pragma unroll
            for (int q = 0; q < 4; q++) acc[mi][ni][q] = 0.f;

    auto issue = [&](int c, int s) {
        uint32_t off = (uint32_t)s * 32768;
#pragma unroll
        for (int it = 0; it < 4; it++) cp16(adst[it] + off, aptr[it] + c * 64);
#pragma unroll
        for (int it = 0; it < 4; it++) cp16(bdst[it] + off, bptr[it] + c * 64);
        CP_COMMIT();
    };

    issue(0, 0);
    if (NK > 1) issue(1, 1);
    if (NK > 2) issue(2, 2);

    uint32_t afr[2][4][4], bfr[2][4][2];
    auto load_frags = [&](uint32_t as, uint32_t bs, int ks, int buf) {
#pragma unroll
        for (int mi = 0; mi < 4; mi++) {
            int row = rowa_b + mi * 16;
            ldsm4(afr[buf][mi], as + row * 128 + (((ks * 2 + kua) ^ (row & 7)) << 4));
        }
#pragma unroll
        for (int ni = 0; ni < 4; ni++) {
            int row = rowb_b + ni * 8;
            ldsm2(bfr[buf][ni], bs + row * 128 + (((ks * 2 + kub) ^ (row & 7)) << 4));
        }
    };

    int stage = 0;
    for (int c = 0; c < NK; c++) {
        int rem = NK - 1 - c;
        if (rem >= 2)      asm volatile("cp.async.wait_group 2;" ::: "memory");
        else if (rem == 1) asm volatile("cp.async.wait_group 1;" ::: "memory");
        else               asm volatile("cp.async.wait_group 0;" ::: "memory");
        __syncthreads();

        uint32_t as = sb + (uint32_t)stage * 32768;
        uint32_t bs = as + 16384;

        load_frags(as, bs, 0, 0);
#pragma unroll
        for (int ks = 0; ks < 4; ks++) {
            int cur = ks & 1;
            if (ks < 3) load_frags(as, bs, ks + 1, cur ^ 1);
#pragma unroll
            for (int mi = 0; mi < 4; mi++)
#pragma unroll
                for (int ni = 0; ni < 4; ni++)
                    mma_f16(acc[mi][ni], afr[cur][mi], bfr[cur][ni]);
        }
        __syncthreads();
        if (c + STAGES < NK) issue(c + STAGES, stage);
        stage = (stage == STAGES - 1) ? 0 : stage + 1;
    }

#pragma unroll
    for (int mi = 0; mi < 4; mi++) {
        int r0t = row0 + warp_m * 64 + mi * 16 + (lane >> 2);
#pragma unroll
        for (int ni = 0; ni < 4; ni++) {
            int col = j0 + warp_n * 32 + ni * 8 + 2 * (lane & 3);
            float bb0 = __ldg(biasG + (size_t)e * NTOT + col);
            float bb1 = __ldg(biasG + (size_t)e * NTOT + col + 1);
            float v0 = acc[mi][ni][0] + bb0, v1 = acc[mi][ni][1] + bb1;
            float v2 = acc[mi][ni][2] + bb0, v3 = acc[mi][ni][3] + bb1;
            if (RELU) {
                v0 = fmaxf(v0, 0.f); v1 = fmaxf(v1, 0.f);
                v2 = fmaxf(v2, 0.f); v3 = fmaxf(v3, 0.f);
            }
            __half2* base = (__half2*)Cg;
            if (r0t < cnt)
                base[(((size_t)e * CAP + r0t) * NTOT + col) >> 1] = __floats2half2_rn(v0, v1);
            if (r0t + 8 < cnt)
                base[(((size_t)e * CAP + r0t + 8) * NTOT + col) >> 1] = __floats2half2_rn(v2, v3);
        }
    }
}

// ---------------- 5) GEMM2: fp16 mma, CTA 128x256x64, warp 64x64, 4 stages --
// stage = A 128x64 (16KB) + B 256x64 (32KB) = 48KB; 4 stages = 192KB; h read ONCE
#define STAGES2 4
#define STAGE2_BYTES 49152
#define SMEM2_BYTES (STAGES2 * STAGE2_BYTES)

__global__ __launch_bounds__(256) void k_mma2(
    const __half* __restrict__ Ag, const __half* __restrict__ Bg,
    const float* __restrict__ biasG, __half* __restrict__ Cg)
{
    constexpr int NK = 16, NTOT = MDIM, KDIM = NK * 64;
    int e = blockIdx.z;
    int cnt = g_cnt[e];
    int row0 = blockIdx.x * 128;
    if (row0 >= cnt) return;

    extern __shared__ char smem[];
    uint32_t sb = smem_to_u32(smem);
    int tid = threadIdx.x, warp = tid >> 5, lane = tid & 31;
    int warp_m = warp & 1, warp_n = warp >> 1;   // 2 x 4 warps, 64x64 tiles

    // cp.async: A 128 rows x 8 chunks (4/thread); B 256 rows x 8 (8/thread)
    const __half* aptr[4]; const __half* bptr[8];
    uint32_t adst[4], bdst[8];
#pragma unroll
    for (int it = 0; it < 4; it++) {
        int idx = it * 256 + tid;
        int row = idx >> 3, chunk = idx & 7;
        int rr = row0 + row; if (rr >= cnt) rr = cnt - 1;
        aptr[it] = Ag + ((size_t)e * CAP + rr) * KDIM + chunk * 8;
        adst[it] = sb + row * 128 + (uint32_t)((chunk ^ (row & 7)) << 4);
    }
#pragma unroll
    for (int it = 0; it < 8; it++) {
        int idx = it * 256 + tid;
        int row = idx >> 3, chunk = idx & 7;
        bptr[it] = Bg + ((size_t)e * NTOT + row) * KDIM + chunk * 8;
        bdst[it] = sb + 16384 + row * 128 + (uint32_t)((chunk ^ (row & 7)) << 4);
    }

    int rowa_b = warp_m * 64 + (lane & 7) + ((lane >> 3) & 1) * 8;  // + mi*16
    int kua = lane >> 4;
    int rowb_b = warp_n * 64 + (lane & 7) + ((lane >> 4) << 3);     // + nj*16
    int kub = (lane >> 3) & 1;

    float acc[4][8][4];
#pragma unroll
    for (int mi = 0; mi < 4; mi++)
#pragma unroll
        for (int ni = 0; ni < 8; ni++)
#pragma unroll
            for (int q = 0; q < 4; q++) acc[mi][ni][q] = 0.f;

    auto issue = [&](int c, int s) {
        uint32_t off = (uint32_t)s * STAGE2_BYTES;
#pragma unroll
        for (int it = 0; it < 4; it++) cp16(adst[it] + off, aptr[it] + c * 64);
#pragma unroll
        for (int it = 0; it < 8; it++) cp16(bdst[it] + off, bptr[it] + c * 64);
        CP_COMMIT();
    };

    issue(0, 0); issue(1, 1); issue(2, 2);

    for (int c = 0; c < NK; c++) {
        int rem = NK - 1 - c;
        if (rem >= 2)      asm volatile("cp.async.wait_group 2;" ::: "memory");
        else if (rem == 1) asm volatile("cp.async.wait_group 1;" ::: "memory");
        else               asm volatile("cp.async.wait_group 0;" ::: "memory");
        __syncthreads();
        if (c + 3 < NK) issue(c + 3, (c + 3) & (STAGES2 - 1));

        uint32_t as = sb + (uint32_t)(c & (STAGES2 - 1)) * STAGE2_BYTES;
        uint32_t bs = as + 16384;
#pragma unroll
        for (int ks = 0; ks < 4; ks++) {
            uint32_t a[4][4];
#pragma unroll
            for (int mi = 0; mi < 4; mi++) {
                int row = rowa_b + mi * 16;
                ldsm4(a[mi], as + row * 128 + (((ks * 2 + kua) ^ (row & 7)) << 4));
            }
#pragma unroll
            for (int nj = 0; nj < 4; nj++) {
                uint32_t b[4];
                int row = rowb_b + nj * 16;
                ldsm4(b, bs + row * 128 + (((ks * 2 + kub) ^ (row & 7)) << 4));
#pragma unroll
                for (int mi = 0; mi < 4; mi++) {
                    mma_f16(acc[mi][nj * 2 + 0], a[mi], b + 0);
                    mma_f16(acc[mi][nj * 2 + 1], a[mi], b + 2);
                }
            }
        }
    }

#pragma unroll
    for (int mi = 0; mi < 4; mi++) {
        int r0t = row0 + warp_m * 64 + mi * 16 + (lane >> 2);
#pragma unroll
        for (int ni = 0; ni < 8; ni++) {
            int col = warp_n * 64 + ni * 8 + 2 * (lane & 3);
            float bb0 = __ldg(biasG + (size_t)e * NTOT + col);
            float bb1 = __ldg(biasG + (size_t)e * NTOT + col + 1);
            float v0 = acc[mi][ni][0] + bb0, v1 = acc[mi][ni][1] + bb1;
            float v2 = acc[mi][ni][2] + bb0, v3 = acc[mi][ni][3] + bb1;
            __half2* base = (__half2*)Cg;
            if (r0t < cnt)
                base[(((size_t)e * CAP + r0t) * NTOT + col) >> 1] = __floats2half2_rn(v0, v1);
            if (r0t + 8 < cnt)
                base[(((size_t)e * CAP + r0t + 8) * NTOT + col) >> 1] = __floats2half2_rn(v2, v3);
        }
    }
}

// ---------------- 6) combine (fp16 eo) ---------------------------------------
__global__ __launch_bounds__(256) void k_combine(float* __restrict__ y) {
    int tid = threadIdx.x;
    int s = blockIdx.x * 4 + (tid >> 6);
    int m = (tid & 63) << 2;
    int sl0 = g_tokslot[s * 2 + 0], sl1 = g_tokslot[s * 2 + 1];
    float v0 = g_topv[s * 2 + 0],  v1 = g_topv[s * 2 + 1];
    float rx = 0.f, ry = 0.f, rz = 0.f, rw = 0.f;
    if (sl0 >= 0) {
        const __half2* p = (const __half2*)(g_eo + (size_t)sl0 * MDIM + m);
        float2 lo = __half22float2(p[0]), hi = __half22float2(p[1]);
        rx += v0 * lo.x; ry += v0 * lo.y; rz += v0 * hi.x; rw += v0 * hi.y;
    }
    if (sl1 >= 0) {
        const __half2* p = (const __half2*)(g_eo + (size_t)sl1 * MDIM + m);
        float2 lo = __half22float2(p[0]), hi = __half22float2(p[1]);
        rx += v1 * lo.x; ry += v1 * lo.y; rz += v1 * hi.x; rw += v1 * hi.y;
    }
    float4 o = {rx, ry, rz, rw};
    *(float4*)&y[(size_t)s * MDIM + m] = o;
}

// ---------------- launch -----------------------------------------------------
extern "C" void kernel_launch(void* const* d_in, const int* in_sizes, int n_in,
                              void* d_out, int out_size) {
    const float* x  = (const float*)d_in[0];
    const float* wg = (const float*)d_in[1];
    const float* w1 = (const float*)d_in[2];
    const float* b1 = (const float*)d_in[3];
    const float* w2 = (const float*)d_in[4];
    const float* b2 = (const float*)d_in[5];
    float* y = (float*)d_out;
    float* lossPtr = (out_size > SNUM * MDIM) ? (y + (size_t)SNUM * MDIM) : nullptr;

    __half *xh, *w1t, *w2t, *hbuf, *eobuf;
    cudaGetSymbolAddress((void**)&xh,   g_xh);
    cudaGetSymbolAddress((void**)&w1t,  g_w1t);
    cudaGetSymbolAddress((void**)&w2t,  g_w2t);
    cudaGetSymbolAddress((void**)&hbuf, g_h);
    cudaGetSymbolAddress((void**)&eobuf, g_eo);

    cudaFuncSetAttribute(k_mma<4, HDIM, true, true>,
                         cudaFuncAttributeMaxDynamicSharedMemorySize, SMEM_BYTES);
    cudaFuncSetAttribute(k_mma2,
                         cudaFuncAttributeMaxDynamicSharedMemorySize, SMEM2_BYTES);

    k_gate <<<NB, 256>>>(x, wg);
    k_transpose<<<dim3(HDIM / 32, MDIM / 32, ENUM), dim3(32, 8)>>>(w1, w1t, MDIM, HDIM);
    k_transpose<<<dim3(MDIM / 32, HDIM / 32, ENUM), dim3(32, 8)>>>(w2, w2t, HDIM, MDIM);
    k_scanA<<<NSEG, 512>>>();
    k_scanB<<<1, 512>>>(lossPtr);
    k_route<<<NB, 256>>>();
    k_mma<4, HDIM, true, true>
        <<<dim3(CAP / 128, HDIM / 128, ENUM), 256, SMEM_BYTES>>>(xh, w1t, b1, hbuf);
    k_mma2<<<dim3(CAP / 128, 1, ENUM), 256, SMEM2_BYTES>>>(hbuf, w2t, b2, eobuf);
    k_combine<<<SNUM / 4, 256>>>(y);
}

// round 17
// speedup vs baseline: 1.0786x; 1.0786x over previous
#include <cuda_runtime.h>
#include <cuda_fp16.h>
#include <cstdint>

#define SNUM 65536
#define MDIM 256
#define ENUM 8
#define HDIM 1024
#define CAP  20480          // TOP_K * int(1.25 * S/E)
#define NB   8192           // gating blocks, 8 tokens each
#define NSEG 128            // scan segments (64 gating blocks each)

// ---------------- scratch (device globals; no allocations allowed) ----------
__device__ int   g_topi[SNUM * 2];
__device__ float g_topv[SNUM * 2];
__device__ int   g_blockcnt[NB * 16];
__device__ int   g_blockoff[NB * 16];     // local exclusive within segment
__device__ float g_blockgate[NB * ENUM];
__device__ int   g_segsum[NSEG * 16];
__device__ int   g_segoff[NSEG * 16];     // exclusive across segments
__device__ float g_gatepart[NSEG * ENUM];
__device__ int   g_k1base[ENUM];
__device__ int   g_cnt[ENUM];
__device__ int   g_src[ENUM * CAP];
__device__ int   g_tokslot[SNUM * 2];
__device__ __half g_xh [(size_t)SNUM * MDIM];          // fp16 x
__device__ __half g_w1t[(size_t)ENUM * HDIM * MDIM];   // [E][1024][256] fp16
__device__ __half g_w2t[(size_t)ENUM * MDIM * HDIM];   // [E][256][1024] fp16
__device__ __half g_h [(size_t)ENUM * CAP * HDIM];     // hidden fp16
__device__ __half g_eo[(size_t)ENUM * CAP * MDIM];     // expert outputs fp16

// ---------------- helpers ----------------------------------------------------
__device__ __forceinline__ uint32_t smem_to_u32(const void* p) {
    uint32_t a;
    asm("{ .reg .u64 t; cvta.to.shared.u64 t, %1; cvt.u32.u64 %0, t; }" : "=r"(a) : "l"(p));
    return a;
}
__device__ __forceinline__ void cp16(uint32_t dst, const void* src) {
    asm volatile("cp.async.cg.shared.global [%0], [%1], 16;" :: "r"(dst), "l"(src) : "memory");
}
#define CP_COMMIT() asm volatile("cp.async.commit_group;" ::: "memory")

__device__ __forceinline__ void ldsm4(uint32_t* r, uint32_t addr) {
    asm volatile("ldmatrix.sync.aligned.m8n8.x4.shared.b16 {%0,%1,%2,%3}, [%4];"
                 : "=r"(r[0]), "=r"(r[1]), "=r"(r[2]), "=r"(r[3]) : "r"(addr));
}
__device__ __forceinline__ void mma_f16(float* c, const uint32_t* a, const uint32_t* b) {
    asm volatile("mma.sync.aligned.m16n8k16.row.col.f32.f16.f16.f32 "
                 "{%0,%1,%2,%3}, {%4,%5,%6,%7}, {%8,%9}, {%0,%1,%2,%3};"
                 : "+f"(c[0]), "+f"(c[1]), "+f"(c[2]), "+f"(c[3])
                 : "r"(a[0]), "r"(a[1]), "r"(a[2]), "r"(a[3]), "r"(b[0]), "r"(b[1]));
}

// ---------------- 0) transpose + fp16 weights --------------------------------
__global__ void k_transpose(const float* __restrict__ in, __half* __restrict__ out,
                            int R, int C) {
    __shared__ float t[32][33];
    int e = blockIdx.z;
    const float* ine = in + (size_t)e * R * C;
    __half* oute = out + (size_t)e * R * C;
    int c0 = blockIdx.x * 32, r0 = blockIdx.y * 32;
    int tx = threadIdx.x, ty = threadIdx.y;
#pragma unroll
    for (int i = 0; i < 4; i++)
        t[ty + i * 8][tx] = ine[(size_t)(r0 + ty + i * 8) * C + c0 + tx];
    __syncthreads();
#pragma unroll
    for (int i = 0; i < 4; i++)
        oute[(size_t)(c0 + ty + i * 8) * R + r0 + tx] = __float2half_rn(t[tx][ty + i * 8]);
}

// ---------------- 1) gating (also emits fp16 x) ------------------------------
__global__ __launch_bounds__(256) void k_gate(const float* __restrict__ x,
                                              const float* __restrict__ wg) {
    __shared__ float wgs[ENUM * MDIM];
    __shared__ int   scnt[16];
    __shared__ float sg[8][ENUM];
    int tid = threadIdx.x;
    for (int i = tid; i < ENUM * MDIM; i += 256) wgs[i] = wg[i];
    if (tid < 16) scnt[tid] = 0;
    __syncthreads();

    int warp = tid >> 5, lane = tid & 31;
    int s = blockIdx.x * 8 + warp;
    const float* xr = x + (size_t)s * MDIM;

    float part[ENUM];
#pragma unroll
    for (int e = 0; e < ENUM; e++) part[e] = 0.f;
#pragma unroll
    for (int i = 0; i < 8; i++) {
        float v = xr[i * 32 + lane];
#pragma unroll
        for (int e = 0; e < ENUM; e++) part[e] += v * wgs[e * MDIM + i * 32 + lane];
    }
    // fused x -> fp16 (row is hot in L1)
    {
        float4 a0 = *(const float4*)(xr + lane * 8);
        float4 a1 = *(const float4*)(xr + lane * 8 + 4);
        __half2 hh[4];
        hh[0] = __floats2half2_rn(a0.x, a0.y);
        hh[1] = __floats2half2_rn(a0.z, a0.w);
        hh[2] = __floats2half2_rn(a1.x, a1.y);
        hh[3] = __floats2half2_rn(a1.z, a1.w);
        *(uint4*)(g_xh + (size_t)s * MDIM + lane * 8) = *(const uint4*)hh;
    }
#pragma unroll
    for (int e = 0; e < ENUM; e++) {
#pragma unroll
        for (int off = 16; off; off >>= 1)
            part[e] += __shfl_xor_sync(0xffffffffu, part[e], off);
    }

    if (lane == 0) {
        float mx = part[0];
#pragma unroll
        for (int e = 1; e < ENUM; e++) mx = fmaxf(mx, part[e]);
        float p[ENUM]; float sum = 0.f;
#pragma unroll
        for (int e = 0; e < ENUM; e++) { p[e] = expf(part[e] - mx); sum += p[e]; }
        float inv = 1.f / sum;
#pragma unroll
        for (int e = 0; e < ENUM; e++) { p[e] *= inv; sg[warp][e] = p[e]; }
        int i0 = 0; float v0 = p[0];
#pragma unroll
        for (int e = 1; e < ENUM; e++) if (p[e] > v0) { v0 = p[e]; i0 = e; }
        int i1 = -1; float v1 = -1.f;
#pragma unroll
        for (int e = 0; e < ENUM; e++) if (e != i0 && p[e] > v1) { v1 = p[e]; i1 = e; }
        g_topi[s * 2 + 0] = i0;  g_topi[s * 2 + 1] = i1;
        g_topv[s * 2 + 0] = v0;  g_topv[s * 2 + 1] = v1;
        atomicAdd(&scnt[i0 * 2 + 0], 1);
        atomicAdd(&scnt[i1 * 2 + 1], 1);
    }
    __syncthreads();
    if (tid < 16) g_blockcnt[blockIdx.x * 16 + tid] = scnt[tid];
    if (tid < ENUM) {
        float a = 0.f;
#pragma unroll
        for (int w = 0; w < 8; w++) a += sg[w][tid];
        g_blockgate[blockIdx.x * ENUM + tid] = a;
    }
}

// ---------------- 2a) segment scan (parallel) --------------------------------
__global__ __launch_bounds__(512) void k_scanA() {
    int seg = blockIdx.x;
    int tid = threadIdx.x, w = tid >> 5, lane = tid & 31;
    int carry = 0;
#pragma unroll
    for (int c = 0; c < 2; c++) {
        int row = seg * 64 + c * 32 + lane;
        int v = g_blockcnt[row * 16 + w];
        int inc = v;
#pragma unroll
        for (int off = 1; off < 32; off <<= 1) {
            int t = __shfl_up_sync(0xffffffffu, inc, off);
            if (lane >= off) inc += t;
        }
        g_blockoff[row * 16 + w] = carry + inc - v;   // local exclusive
        carry += __shfl_sync(0xffffffffu, inc, 31);
    }
    if (lane == 0) g_segsum[seg * 16 + w] = carry;
    if (w < ENUM) {   // fixed-order segment gate sum
        float a = g_blockgate[(seg * 64 + lane) * ENUM + w]
                + g_blockgate[(seg * 64 + 32 + lane) * ENUM + w];
#pragma unroll
        for (int off = 16; off; off >>= 1)
            a += __shfl_xor_sync(0xffffffffu, a, off);
        if (lane == 0) g_gatepart[seg * ENUM + w] = a;
    }
}

// ---------------- 2b) top-level scan + loss ----------------------------------
__global__ __launch_bounds__(512) void k_scanB(float* lossPtr) {
    int tid = threadIdx.x, w = tid >> 5, lane = tid & 31;
    __shared__ int   s_tot[16];
    __shared__ float s_gs[ENUM];
    int carry = 0;
#pragma unroll
    for (int c = 0; c < NSEG / 32; c++) {
        int seg = c * 32 + lane;
        int v = g_segsum[seg * 16 + w];
        int inc = v;
#pragma unroll
        for (int off = 1; off < 32; off <<= 1) {
            int t = __shfl_up_sync(0xffffffffu, inc, off);
            if (lane >= off) inc += t;
        }
        g_segoff[seg * 16 + w] = carry + inc - v;
        carry += __shfl_sync(0xffffffffu, inc, 31);
    }
    if (lane == 0) s_tot[w] = carry;
    if (w < ENUM) {
        float a = 0.f;
#pragma unroll
        for (int c = 0; c < NSEG / 32; c++)
            a += g_gatepart[(c * 32 + lane) * ENUM + w];
#pragma unroll
        for (int off = 16; off; off >>= 1)
            a += __shfl_xor_sync(0xffffffffu, a, off);
        if (lane == 0) s_gs[w] = a;
    }
    __syncthreads();
    if (tid == 0) {
        float loss = 0.f;
        for (int e = 0; e < ENUM; e++) {
            float me = s_gs[e] / (float)SNUM;
            float ce = (float)s_tot[e * 2] / (float)SNUM;
            loss += me * ce;
        }
        loss *= (float)ENUM;
        if (lossPtr) *lossPtr = loss;
        for (int e = 0; e < ENUM; e++) {
            g_k1base[e] = s_tot[e * 2];
            int t = s_tot[e * 2] + s_tot[e * 2 + 1];
            g_cnt[e] = t < CAP ? t : CAP;
        }
    }
}

// ---------------- 3) routing -------------------------------------------------
__global__ __launch_bounds__(256) void k_route() {
    __shared__ int ch[8][2];
    int tid = threadIdx.x, warp = tid >> 5, lane = tid & 31;
    int s = blockIdx.x * 8 + warp;
    if (lane < 2) ch[warp][lane] = g_topi[s * 2 + lane];
    __syncthreads();
    if (tid < 16) {
        int t = tid >> 1, k = tid & 1;
        int s2 = blockIdx.x * 8 + t;
        int e = ch[t][k];
        int rank = 0;
#pragma unroll
        for (int u = 0; u < 8; u++) rank += (u < t) && (ch[u][k] == e);
        int idx = e * 2 + k;
        int pos = g_blockoff[blockIdx.x * 16 + idx]
                + g_segoff[(blockIdx.x >> 6) * 16 + idx]
                + rank + (k ? g_k1base[e] : 0);
        int slot = -1;
        if (pos < CAP) { slot = e * CAP + pos; g_src[slot] = s2; }
        g_tokslot[s2 * 2 + k] = slot;
    }
}

// ---------------- 4/5) fp16 mma GEMM: CTA 128x128x64, 4 warps x (64x64) -----
// stage = A 128x64 (16KB) + B 128x64 (16KB) = 32KB; 3 stages = 96KB; 2 CTA/SM
#define STAGES 3
#define SMEM_BYTES (STAGES * 32768)

template<int NK, int NTOT, bool GATHER, bool RELU>
__global__ __launch_bounds__(128, 2) void k_mma(
    const __half* __restrict__ Ag, const __half* __restrict__ Bg,
    const float* __restrict__ biasG, __half* __restrict__ Cg)
{
    constexpr int KDIM = NK * 64;
    int e = blockIdx.z;
    int cnt = g_cnt[e];
    int row0 = blockIdx.x * 128;
    if (row0 >= cnt) return;
    int j0 = blockIdx.y * 128;

    extern __shared__ char smem[];
    uint32_t sb = smem_to_u32(smem);
    __shared__ int s_src[128];
    int tid = threadIdx.x, warp = tid >> 5, lane = tid & 31;
    int warp_m = warp & 1, warp_n = (warp >> 1) & 1;   // 2 x 2 warps, 64x64 tiles

    if (GATHER) {
        int r = row0 + tid;
        s_src[tid] = g_src[e * CAP + (r < cnt ? r : cnt - 1)];
    }
    __syncthreads();

    // cp.async: chunk (16B unit) and row-low-bits are invariant per thread.
    // thread covers rows (tid>>3) + it*16, it = 0..7, chunk = tid&7.
    int chunk = tid & 7;
    int rbase = tid >> 3;                       // 0..15
    uint32_t sw = (uint32_t)((chunk ^ (rbase & 7)) << 4);
    uint32_t adst0 = sb + rbase * 128 + sw;
    uint32_t bdst0 = sb + 16384 + rbase * 128 + sw;

    const __half* aptr[8];
#pragma unroll
    for (int it = 0; it < 8; it++) {
        int row = it * 16 + rbase;
        if (GATHER) {
            aptr[it] = Ag + (size_t)s_src[row] * KDIM + chunk * 8;
        } else {
            int rr = row0 + row; if (rr >= cnt) rr = cnt - 1;
            aptr[it] = Ag + ((size_t)e * CAP + rr) * KDIM + chunk * 8;
        }
    }
    const __half* bbase = Bg + ((size_t)e * NTOT + j0 + rbase) * KDIM + chunk * 8;

    // ldmatrix per-thread bases (A: 16-row x 2-kunit groups; B: k_mma2-proven map)
    int rowa_b = warp_m * 64 + (lane & 7) + ((lane >> 3) & 1) * 8;  // + mi*16
    int kua = lane >> 4;
    int rowb_b = warp_n * 64 + (lane & 7) + ((lane >> 4) << 3);     // + nj*16
    int kub = (lane >> 3) & 1;

    float acc[4][8][4];
#pragma unroll
    for (int mi = 0; mi < 4; mi++)
#pragma unroll
        for (int ni = 0; ni < 8; ni++)
#pragma unroll
            for (int q = 0; q < 4; q++) acc[mi][ni][q] = 0.f;

    auto issue = [&](int c, int s) {
        uint32_t off = (uint32_t)s * 32768;
#pragma unroll
        for (int it = 0; it < 8; it++)
            cp16(adst0 + it * 2048 + off, aptr[it] + c * 64);
#pragma unroll
        for (int it = 0; it < 8; it++)
            cp16(bdst0 + it * 2048 + off, bbase + (size_t)it * 16 * KDIM + c * 64);
        CP_COMMIT();
    };

    issue(0, 0);
    if (NK > 1) issue(1, 1);
    if (NK > 2) issue(2, 2);

    int stage = 0;
    for (int c = 0; c < NK; c++) {
        int rem = NK - 1 - c;
        if (rem >= 2)      asm volatile("cp.async.wait_group 2;" ::: "memory");
        else if (rem == 1) asm volatile("cp.async.wait_group 1;" ::: "memory");
        else               asm volatile("cp.async.wait_group 0;" ::: "memory");
        __syncthreads();

        uint32_t as = sb + (uint32_t)stage * 32768;
        uint32_t bs = as + 16384;
#pragma unroll
        for (int ks = 0; ks < 4; ks++) {
            uint32_t a[4][4];
#pragma unroll
            for (int mi = 0; mi < 4; mi++) {
                int row = rowa_b + mi * 16;
                ldsm4(a[mi], as + row * 128 + (((ks * 2 + kua) ^ (row & 7)) << 4));
            }
#pragma unroll
            for (int nj = 0; nj < 4; nj++) {
                uint32_t b[4];
                int row = rowb_b + nj * 16;
                ldsm4(b, bs + row * 128 + (((ks * 2 + kub) ^ (row & 7)) << 4));
#pragma unroll
                for (int mi = 0; mi < 4; mi++) {
                    mma_f16(acc[mi][nj * 2 + 0], a[mi], b + 0);
                    mma_f16(acc[mi][nj * 2 + 1], a[mi], b + 2);
                }
            }
        }
        __syncthreads();
        if (c + STAGES < NK) issue(c + STAGES, stage);
        stage = (stage == STAGES - 1) ? 0 : stage + 1;
    }

    // epilogue (fp16 out)
#pragma unroll
    for (int mi = 0; mi < 4; mi++) {
        int r0t = row0 + warp_m * 64 + mi * 16 + (lane >> 2);
#pragma unroll
        for (int ni = 0; ni < 8; ni++) {
            int col = j0 + warp_n * 64 + ni * 8 + 2 * (lane & 3);
            float bb0 = __ldg(biasG + (size_t)e * NTOT + col);
            float bb1 = __ldg(biasG + (size_t)e * NTOT + col + 1);
            float v0 = acc[mi][ni][0] + bb0, v1 = acc[mi][ni][1] + bb1;
            float v2 = acc[mi][ni][2] + bb0, v3 = acc[mi][ni][3] + bb1;
            if (RELU) {
                v0 = fmaxf(v0, 0.f); v1 = fmaxf(v1, 0.f);
                v2 = fmaxf(v2, 0.f); v3 = fmaxf(v3, 0.f);
            }
            __half2* base = (__half2*)Cg;
            if (r0t < cnt)
                base[(((size_t)e * CAP + r0t) * NTOT + col) >> 1] = __floats2half2_rn(v0, v1);
            if (r0t + 8 < cnt)
                base[(((size_t)e * CAP + r0t + 8) * NTOT + col) >> 1] = __floats2half2_rn(v2, v3);
        }
    }
}

// ---------------- 6) combine (fp16 eo) ---------------------------------------
__global__ __launch_bounds__(256) void k_combine(float* __restrict__ y) {
    int tid = threadIdx.x;
    int s = blockIdx.x * 4 + (tid >> 6);
    int m = (tid & 63) << 2;
    int sl0 = g_tokslot[s * 2 + 0], sl1 = g_tokslot[s * 2 + 1];
    float v0 = g_topv[s * 2 + 0],  v1 = g_topv[s * 2 + 1];
    float rx = 0.f, ry = 0.f, rz = 0.f, rw = 0.f;
    if (sl0 >= 0) {
        const __half2* p = (const __half2*)(g_eo + (size_t)sl0 * MDIM + m);
        float2 lo = __half22float2(p[0]), hi = __half22float2(p[1]);
        rx += v0 * lo.x; ry += v0 * lo.y; rz += v0 * hi.x; rw += v0 * hi.y;
    }
    if (sl1 >= 0) {
        const __half2* p = (const __half2*)(g_eo + (size_t)sl1 * MDIM + m);
        float2 lo = __half22float2(p[0]), hi = __half22float2(p[1]);
        rx += v1 * lo.x; ry += v1 * lo.y; rz += v1 * hi.x; rw += v1 * hi.y;
    }
    float4 o = {rx, ry, rz, rw};
    *(float4*)&y[(size_t)s * MDIM + m] = o;
}

// ---------------- launch -----------------------------------------------------
extern "C" void kernel_launch(void* const* d_in, const int* in_sizes, int n_in,
                              void* d_out, int out_size) {
    const float* x  = (const float*)d_in[0];
    const float* wg = (const float*)d_in[1];
    const float* w1 = (const float*)d_in[2];
    const float* b1 = (const float*)d_in[3];
    const float* w2 = (const float*)d_in[4];
    const float* b2 = (const float*)d_in[5];
    float* y = (float*)d_out;
    float* lossPtr = (out_size > SNUM * MDIM) ? (y + (size_t)SNUM * MDIM) : nullptr;

    __half *xh, *w1t, *w2t, *hbuf, *eobuf;
    cudaGetSymbolAddress((void**)&xh,   g_xh);
    cudaGetSymbolAddress((void**)&w1t,  g_w1t);
    cudaGetSymbolAddress((void**)&w2t,  g_w2t);
    cudaGetSymbolAddress((void**)&hbuf, g_h);
    cudaGetSymbolAddress((void**)&eobuf, g_eo);

    cudaFuncSetAttribute(k_mma<4, HDIM, true, true>,
                         cudaFuncAttributeMaxDynamicSharedMemorySize, SMEM_BYTES);
    cudaFuncSetAttribute(k_mma<16, MDIM, false, false>,
                         cudaFuncAttributeMaxDynamicSharedMemorySize, SMEM_BYTES);

    k_gate <<<NB, 256>>>(x, wg);
    k_transpose<<<dim3(HDIM / 32, MDIM / 32, ENUM), dim3(32, 8)>>>(w1, w1t, MDIM, HDIM);
    k_transpose<<<dim3(MDIM / 32, HDIM / 32, ENUM), dim3(32, 8)>>>(w2, w2t, HDIM, MDIM);
    k_scanA<<<NSEG, 512>>>();
    k_scanB<<<1, 512>>>(lossPtr);
    k_route<<<NB, 256>>>();
    k_mma<4, HDIM, true, true>
        <<<dim3(CAP / 128, HDIM / 128, ENUM), 128, SMEM_BYTES>>>(xh, w1t, b1, hbuf);
    k_mma<16, MDIM, false, false>
        <<<dim3(CAP / 128, MDIM / 128, ENUM), 128, SMEM_BYTES>>>(hbuf, w2t, b2, eobuf);
    k_combine<<<SNUM / 4, 256>>>(y);
}